// round 2
// baseline (speedup 1.0000x reference)
#include <cuda_runtime.h>

#define NN 1024
#define H2 60
#define DEP 10
#define DOUT 70
#define NTYPE 50
#define TSTRIDE 72   // padded row stride for T (float4/float2-friendly)

// Scratch (static device arrays — no allocation)
__device__ float g_hW[NN * DOUT];
__device__ float g_eWb[NTYPE * DOUT];
__device__ float g_T[NN * NTYPE * TSTRIDE];   // 14.75 MB

// ---------------------------------------------------------------------------
// Kernel A: hW = h @ W[:H2]   and   eWb = emb @ W[H2:] + b
// ---------------------------------------------------------------------------
__global__ __launch_bounds__(96) void precompute_kernel(
    const float* __restrict__ h,
    const float* __restrict__ emb,
    const float* __restrict__ W,
    const float* __restrict__ bvec)
{
    int blk = blockIdx.x;
    int f = threadIdx.x;
    if (f >= DOUT) return;
    if (blk < NN) {
        const float* hr = h + blk * H2;
        float s = 0.f;
        #pragma unroll 4
        for (int c = 0; c < H2; c++) s += hr[c] * W[c * DOUT + f];
        g_hW[blk * DOUT + f] = s;
    } else {
        int t = blk - NN;
        const float* er = emb + t * DEP;
        float s = bvec[f];
        #pragma unroll
        for (int c = 0; c < DEP; c++) s += er[c] * W[(H2 + c) * DOUT + f];
        g_eWb[t * DOUT + f] = s;
    }
}

// ---------------------------------------------------------------------------
// Kernel B: per row i — masked type histogram, T table, s_in
// ---------------------------------------------------------------------------
__global__ __launch_bounds__(128) void row_kernel(
    const int* __restrict__ matrix,
    const int* __restrict__ mask,
    float* __restrict__ out)   // out[0 .. N*DOUT) = s_in
{
    int i = blockIdx.x;
    int tid = threadIdx.x;
    __shared__ int cnt[NTYPE];
    if (tid < NTYPE) cnt[tid] = 0;
    __syncthreads();

    const int* mrow = matrix + (size_t)i * 2 * NN;
    const int* krow = mask   + (size_t)i * 2 * NN;
    for (int e = tid; e < 2 * NN; e += 128) {
        int m = krow[e];
        if (m) atomicAdd(&cnt[mrow[e]], 1);
    }
    __syncthreads();

    if (tid < DOUT) {
        float hw = g_hW[i * DOUT + tid];
        float acc = 0.f;
        float* Trow = g_T + (size_t)i * NTYPE * TSTRIDE + tid;
        #pragma unroll 5
        for (int t = 0; t < NTYPE; t++) {
            float v = tanhf(hw + g_eWb[t * DOUT + tid]);
            Trow[t * TSTRIDE] = v;
            acc += (float)cnt[t] * v;
        }
        out[i * DOUT + tid] = acc;
    }
}

// ---------------------------------------------------------------------------
// Kernel C: s_out gather.  Grid (4 j-tiles, 37 i-tiles) = 148 blocks (1/SM).
// Per i: stage T[i] (50x72 f32) + packed type codes in SMEM (reg-prefetched),
// each warp owns 16 j-columns; lanes cover dims as float2:
//   lanes 0..31 -> dims [2*lane, 2*lane+1], lanes 0..2 -> dims [64+2*lane, 65+2*lane]
// ---------------------------------------------------------------------------
#define JT 256
#define IT 28
#define CWARPS 16
#define CTHREADS 512
#define JPW (JT / CWARPS)   // 16

__global__ __launch_bounds__(CTHREADS, 1) void col_kernel(
    const int* __restrict__ matrix,
    const int* __restrict__ mask,
    float* __restrict__ sout)   // points at out + N*DOUT, pre-zeroed
{
    __shared__ float Tsh[NTYPE * TSTRIDE];   // 3600 f32 = 14.4 KB
    __shared__ int codes[JT];

    const int jbase = blockIdx.x * JT;
    const int i0 = blockIdx.y * IT;
    const int i1 = min(i0 + IT, NN);
    const int tid = threadIdx.x;
    const int w = tid >> 5, lane = tid & 31;

    float2 a0[JPW], a1[JPW];
    #pragma unroll
    for (int q = 0; q < JPW; q++) {
        a0[q] = make_float2(0.f, 0.f);
        a1[q] = make_float2(0.f, 0.f);
    }

    float4 pf0, pf1;
    int pcode = 0;

    // initial load+store for i0
    {
        const float4* Tg = (const float4*)(g_T + (size_t)i0 * NTYPE * TSTRIDE);
        if (tid < 900) pf0 = Tg[tid];
        if (tid < 388) pf1 = Tg[tid + 512];
        if (tid < JT) {
            int j = jbase + tid;
            int2 tt = ((const int2*)matrix)[(size_t)i0 * NN + j];
            int2 mm = ((const int2*)mask)[(size_t)i0 * NN + j];
            pcode = (mm.x ? tt.x : 0xFF) | ((mm.y ? tt.y : 0xFF) << 8);
        }
        float4* Ts4 = (float4*)Tsh;
        if (tid < 900) Ts4[tid] = pf0;
        if (tid < 388) Ts4[tid + 512] = pf1;
        if (tid < JT) codes[tid] = pcode;
    }

    for (int i = i0; i < i1; i++) {
        __syncthreads();   // stage for i is visible

        // prefetch i+1 into registers (latency hidden by gather below)
        const bool has_next = (i + 1) < i1;
        if (has_next) {
            const float4* Tg = (const float4*)(g_T + (size_t)(i + 1) * NTYPE * TSTRIDE);
            if (tid < 900) pf0 = Tg[tid];
            if (tid < 388) pf1 = Tg[tid + 512];
            if (tid < JT) {
                int j = jbase + tid;
                int2 tt = ((const int2*)matrix)[(size_t)(i + 1) * NN + j];
                int2 mm = ((const int2*)mask)[(size_t)(i + 1) * NN + j];
                pcode = (mm.x ? tt.x : 0xFF) | ((mm.y ? tt.y : 0xFF) << 8);
            }
        }

        // gather for row i
        const int jb = w * JPW;
        #pragma unroll
        for (int q = 0; q < JPW; q++) {
            int code = codes[jb + q];         // warp-uniform broadcast
            int c0 = code & 0xFF;
            int c1 = (code >> 8) & 0xFF;
            if (c0 != 0xFF) {
                const float2* Tr = (const float2*)(Tsh + c0 * TSTRIDE);
                float2 v = Tr[lane];
                a0[q].x += v.x; a0[q].y += v.y;
                if (lane < 3) {
                    float2 u = Tr[32 + lane];
                    a1[q].x += u.x; a1[q].y += u.y;
                }
            }
            if (c1 != 0xFF) {
                const float2* Tr = (const float2*)(Tsh + c1 * TSTRIDE);
                float2 v = Tr[lane];
                a0[q].x += v.x; a0[q].y += v.y;
                if (lane < 3) {
                    float2 u = Tr[32 + lane];
                    a1[q].x += u.x; a1[q].y += u.y;
                }
            }
        }

        __syncthreads();   // all gathers on this stage done

        if (has_next) {
            float4* Ts4 = (float4*)Tsh;
            if (tid < 900) Ts4[tid] = pf0;
            if (tid < 388) Ts4[tid + 512] = pf1;
            if (tid < JT) codes[tid] = pcode;
        }
    }

    // combine partials across the 37 i-tiles
    #pragma unroll
    for (int q = 0; q < JPW; q++) {
        int j = jbase + w * JPW + q;
        atomicAdd(&sout[j * DOUT + 2 * lane],     a0[q].x);
        atomicAdd(&sout[j * DOUT + 2 * lane + 1], a0[q].y);
        if (lane < 3) {
            atomicAdd(&sout[j * DOUT + 64 + 2 * lane], a1[q].x);
            atomicAdd(&sout[j * DOUT + 65 + 2 * lane], a1[q].y);
        }
    }
}

// ---------------------------------------------------------------------------
extern "C" void kernel_launch(void* const* d_in, const int* in_sizes, int n_in,
                              void* d_out, int out_size)
{
    const float* h      = (const float*)d_in[0];
    const float* emb    = (const float*)d_in[1];
    const float* W      = (const float*)d_in[2];
    const float* bvec   = (const float*)d_in[3];
    const int*   matrix = (const int*)d_in[4];
    const int*   mask   = (const int*)d_in[5];
    float* out = (float*)d_out;

    // zero s_out half (atomically accumulated); s_in half written directly
    cudaMemsetAsync(out + NN * DOUT, 0, NN * DOUT * sizeof(float));

    precompute_kernel<<<NN + NTYPE, 96>>>(h, emb, W, bvec);
    row_kernel<<<NN, 128>>>(matrix, mask, out);
    col_kernel<<<dim3(4, 37), CTHREADS>>>(matrix, mask, out + NN * DOUT);
}

// round 4
// speedup vs baseline: 1.1795x; 1.1795x over previous
#include <cuda_runtime.h>
#include <cstdint>

#define NN 1024
#define H2 60
#define DEP 10
#define DOUT 70
#define NTYPE 50
#define TSTRIDE 72   // padded T row stride (float4-friendly)

// Scratch (static device array — no allocation)
__device__ float g_T[NN * NTYPE * TSTRIDE];   // 14.75 MB

// tanh(x) = 1 - 2/(exp(2x)+1), via SFU ex2/rcp.
// x->+inf: e=inf, rcp=0 -> 1.  x->-inf: e=0, rcp(1)=1 -> -1. No clamp needed.
__device__ __forceinline__ float fast_tanh(float x) {
    float e, r;
    asm("ex2.approx.f32 %0, %1;" : "=f"(e) : "f"(x * 2.885390082f)); // 2*log2(e)
    asm("rcp.approx.f32 %0, %1;" : "=f"(r) : "f"(e + 1.0f));
    return fmaf(-2.0f, r, 1.0f);
}

// ---------------------------------------------------------------------------
// Kernel R (block = row i): histogram of masked types, hW projection,
// T table (tanh), s_in, and zero s_out row i.
// ---------------------------------------------------------------------------
__global__ __launch_bounds__(128) void row_kernel(
    const float* __restrict__ h,
    const float* __restrict__ emb,
    const float* __restrict__ W,
    const float* __restrict__ bvec,
    const int* __restrict__ matrix,
    const int* __restrict__ mask,
    float* __restrict__ out)      // [0..N*DOUT) = s_in, [N*DOUT..) = s_out
{
    const int i = blockIdx.x;
    const int tid = threadIdx.x;
    const int w = tid >> 5;

    __shared__ int   cnt[4][64];        // warp-private histograms (padded)
    __shared__ float hsh[H2];
    __shared__ float esh[NTYPE * DEP];  // 500 floats

    for (int k = tid; k < 4 * 64; k += 128) ((int*)cnt)[k] = 0;
    if (tid < H2) hsh[tid] = h[i * H2 + tid];
    for (int k = tid; k < NTYPE * DEP; k += 128) esh[k] = emb[k];
    __syncthreads();

    // masked type histogram (int4 loads, warp-private counters)
    const int4* m4 = (const int4*)(matrix + (size_t)i * 2 * NN);
    const int4* k4 = (const int4*)(mask   + (size_t)i * 2 * NN);
    for (int e = tid; e < 512; e += 128) {
        int4 mm = m4[e];
        int4 kk = k4[e];
        if (kk.x) atomicAdd(&cnt[w][mm.x], 1);
        if (kk.y) atomicAdd(&cnt[w][mm.y], 1);
        if (kk.z) atomicAdd(&cnt[w][mm.z], 1);
        if (kk.w) atomicAdd(&cnt[w][mm.w], 1);
    }
    __syncthreads();
    if (tid < NTYPE)
        cnt[0][tid] += cnt[1][tid] + cnt[2][tid] + cnt[3][tid];
    __syncthreads();

    if (tid < DOUT) {
        const int f = tid;
        // hW[i][f]
        float hw = 0.f;
        #pragma unroll 6
        for (int c = 0; c < H2; c++) hw = fmaf(hsh[c], W[c * DOUT + f], hw);
        // W rows for the embedding part + bias
        float Wc[DEP];
        #pragma unroll
        for (int c = 0; c < DEP; c++) Wc[c] = W[(H2 + c) * DOUT + f];
        const float bf = bvec[f];

        float acc = 0.f;
        float* Trow = g_T + (size_t)i * NTYPE * TSTRIDE + f;
        #pragma unroll 2
        for (int t = 0; t < NTYPE; t++) {
            float ew = bf;
            #pragma unroll
            for (int c = 0; c < DEP; c++) ew = fmaf(esh[t * DEP + c], Wc[c], ew);
            float v = fast_tanh(hw + ew);
            Trow[t * TSTRIDE] = v;
            acc = fmaf((float)cnt[0][t], v, acc);
        }
        out[i * DOUT + f] = acc;               // s_in
        out[NN * DOUT + i * DOUT + f] = 0.f;   // zero s_out row i for kernel C
    }
}

// ---------------------------------------------------------------------------
// Kernel C: s_out gather. Grid (4 j-tiles, 37 i-tiles) = 148 blocks (1/SM).
// cp.async double-buffered staging of T[i] (50x72 f32) + packed codes,
// one barrier per i. Each warp owns 16 j-columns; lanes cover dims as float2.
// ---------------------------------------------------------------------------
#define JT 256
#define IT 28
#define CTHREADS 512
#define JPW 16   // JT / 16 warps

__device__ __forceinline__ void cp16(unsigned dst, const void* src) {
    asm volatile("cp.async.cg.shared.global [%0], [%1], 16;" :: "r"(dst), "l"(src));
}

__global__ __launch_bounds__(CTHREADS, 1) void col_kernel(
    const int* __restrict__ matrix,
    const int* __restrict__ mask,
    float* __restrict__ sout)   // out + N*DOUT, zeroed by row_kernel
{
    __shared__ float Tsh[2][NTYPE * TSTRIDE];   // 2 x 14.4 KB
    __shared__ int   codes[2][JT];

    const int jbase = blockIdx.x * JT;
    const int i0 = blockIdx.y * IT;
    const int i1 = min(i0 + IT, NN);
    const int tid = threadIdx.x;
    const int w = tid >> 5, lane = tid & 31;

    float2 a0[JPW], a1[JPW];
    #pragma unroll
    for (int q = 0; q < JPW; q++) {
        a0[q] = make_float2(0.f, 0.f);
        a1[q] = make_float2(0.f, 0.f);
    }

    const unsigned ts0 = (unsigned)__cvta_generic_to_shared(&Tsh[0][0]);
    const unsigned ts1 = (unsigned)__cvta_generic_to_shared(&Tsh[1][0]);

    // prologue: stage i0
    {
        const float4* src = (const float4*)(g_T + (size_t)i0 * NTYPE * TSTRIDE);
        cp16(ts0 + tid * 16, src + tid);
        if (tid < 388) cp16(ts0 + (512 + tid) * 16, src + 512 + tid);
        asm volatile("cp.async.commit_group;");
    }
    int pcode = 0;
    if (tid < JT) {
        int j = jbase + tid;
        int2 tt = ((const int2*)matrix)[(size_t)i0 * NN + j];
        int2 mm = ((const int2*)mask)[(size_t)i0 * NN + j];
        pcode = (mm.x ? tt.x : 0xFF) | ((mm.y ? tt.y : 0xFF) << 8);
    }

    for (int i = i0; i < i1; i++) {
        const int buf = (i - i0) & 1;

        asm volatile("cp.async.wait_group 0;" ::: "memory");  // T[i] landed
        if (tid < JT) codes[buf][tid] = pcode;
        __syncthreads();   // T[i]+codes[i] visible; gathers of i-1 from buf^1 done

        if (i + 1 < i1) {
            // stage i+1 into other buffer (overlaps with gather below)
            const float4* src = (const float4*)(g_T + (size_t)(i + 1) * NTYPE * TSTRIDE);
            const unsigned dst = (buf ^ 1) ? ts1 : ts0;
            cp16(dst + tid * 16, src + tid);
            if (tid < 388) cp16(dst + (512 + tid) * 16, src + 512 + tid);
            asm volatile("cp.async.commit_group;");
            if (tid < JT) {
                int j = jbase + tid;
                int2 tt = ((const int2*)matrix)[(size_t)(i + 1) * NN + j];
                int2 mm = ((const int2*)mask)[(size_t)(i + 1) * NN + j];
                pcode = (mm.x ? tt.x : 0xFF) | ((mm.y ? tt.y : 0xFF) << 8);
            }
        }

        // gather row i
        const float* Tb = Tsh[buf];
        const int* cb = codes[buf];
        const int jb = w * JPW;
        #pragma unroll
        for (int q = 0; q < JPW; q++) {
            int code = cb[jb + q];            // warp-uniform broadcast
            int c0 = code & 0xFF;
            int c1 = (code >> 8) & 0xFF;
            if (c0 != 0xFF) {
                const float2* Tr = (const float2*)(Tb + c0 * TSTRIDE);
                float2 v = Tr[lane];
                a0[q].x += v.x; a0[q].y += v.y;
                if (lane < 3) {
                    float2 u = Tr[32 + lane];
                    a1[q].x += u.x; a1[q].y += u.y;
                }
            }
            if (c1 != 0xFF) {
                const float2* Tr = (const float2*)(Tb + c1 * TSTRIDE);
                float2 v = Tr[lane];
                a0[q].x += v.x; a0[q].y += v.y;
                if (lane < 3) {
                    float2 u = Tr[32 + lane];
                    a1[q].x += u.x; a1[q].y += u.y;
                }
            }
        }
    }

    // combine partials across the 37 i-tiles
    #pragma unroll
    for (int q = 0; q < JPW; q++) {
        int j = jbase + w * JPW + q;
        atomicAdd(&sout[j * DOUT + 2 * lane],     a0[q].x);
        atomicAdd(&sout[j * DOUT + 2 * lane + 1], a0[q].y);
        if (lane < 3) {
            atomicAdd(&sout[j * DOUT + 64 + 2 * lane], a1[q].x);
            atomicAdd(&sout[j * DOUT + 65 + 2 * lane], a1[q].y);
        }
    }
}

// ---------------------------------------------------------------------------
extern "C" void kernel_launch(void* const* d_in, const int* in_sizes, int n_in,
                              void* d_out, int out_size)
{
    const float* h      = (const float*)d_in[0];
    const float* emb    = (const float*)d_in[1];
    const float* W      = (const float*)d_in[2];
    const float* bvec   = (const float*)d_in[3];
    const int*   matrix = (const int*)d_in[4];
    const int*   mask   = (const int*)d_in[5];
    float* out = (float*)d_out;

    row_kernel<<<NN, 128>>>(h, emb, W, bvec, matrix, mask, out);
    col_kernel<<<dim3(4, 37), CTHREADS>>>(matrix, mask, out + NN * DOUT);
}

// round 5
// speedup vs baseline: 1.4845x; 1.2586x over previous
#include <cuda_runtime.h>
#include <cstdint>

#define NN 1024
#define H2 60
#define DEP 10
#define DOUT 70
#define NTYPE 50
#define TSTRIDE 72   // padded T row stride (float4-friendly)
#define TROWS 51     // 50 real type rows + 1 zero sentinel row

// Scratch (static device array — no allocation)
__device__ float g_T[NN * NTYPE * TSTRIDE];   // 14.75 MB

// tanh(x) = 1 - 2/(exp(2x)+1), via SFU ex2/rcp.
__device__ __forceinline__ float fast_tanh(float x) {
    float e, r;
    asm("ex2.approx.f32 %0, %1;" : "=f"(e) : "f"(x * 2.885390082f)); // 2*log2(e)
    asm("rcp.approx.f32 %0, %1;" : "=f"(r) : "f"(e + 1.0f));
    return fmaf(-2.0f, r, 1.0f);
}

// ---------------------------------------------------------------------------
// Kernel R (block = row i): histogram of masked types, hW projection,
// T table (tanh), s_in, and zero s_out row i.
// ---------------------------------------------------------------------------
__global__ __launch_bounds__(128) void row_kernel(
    const float* __restrict__ h,
    const float* __restrict__ emb,
    const float* __restrict__ W,
    const float* __restrict__ bvec,
    const int* __restrict__ matrix,
    const int* __restrict__ mask,
    float* __restrict__ out)      // [0..N*DOUT) = s_in, [N*DOUT..) = s_out
{
    const int i = blockIdx.x;
    const int tid = threadIdx.x;
    const int w = tid >> 5;

    __shared__ int   cnt[4][64];        // warp-private histograms (padded)
    __shared__ float hsh[H2];
    __shared__ float esh[NTYPE * DEP];  // 500 floats

    for (int k = tid; k < 4 * 64; k += 128) ((int*)cnt)[k] = 0;
    if (tid < H2) hsh[tid] = h[i * H2 + tid];
    for (int k = tid; k < NTYPE * DEP; k += 128) esh[k] = emb[k];
    __syncthreads();

    // masked type histogram (int4 loads, warp-private counters)
    const int4* m4 = (const int4*)(matrix + (size_t)i * 2 * NN);
    const int4* k4 = (const int4*)(mask   + (size_t)i * 2 * NN);
    for (int e = tid; e < 512; e += 128) {
        int4 mm = m4[e];
        int4 kk = k4[e];
        if (kk.x) atomicAdd(&cnt[w][mm.x], 1);
        if (kk.y) atomicAdd(&cnt[w][mm.y], 1);
        if (kk.z) atomicAdd(&cnt[w][mm.z], 1);
        if (kk.w) atomicAdd(&cnt[w][mm.w], 1);
    }
    __syncthreads();
    if (tid < NTYPE)
        cnt[0][tid] += cnt[1][tid] + cnt[2][tid] + cnt[3][tid];
    __syncthreads();

    if (tid < DOUT) {
        const int f = tid;
        float hw = 0.f;
        #pragma unroll 6
        for (int c = 0; c < H2; c++) hw = fmaf(hsh[c], W[c * DOUT + f], hw);
        float Wc[DEP];
        #pragma unroll
        for (int c = 0; c < DEP; c++) Wc[c] = W[(H2 + c) * DOUT + f];
        const float bf = bvec[f];

        float acc = 0.f;
        float* Trow = g_T + (size_t)i * NTYPE * TSTRIDE + f;
        #pragma unroll 2
        for (int t = 0; t < NTYPE; t++) {
            float ew = bf;
            #pragma unroll
            for (int c = 0; c < DEP; c++) ew = fmaf(esh[t * DEP + c], Wc[c], ew);
            float v = fast_tanh(hw + ew);
            Trow[t * TSTRIDE] = v;
            acc = fmaf((float)cnt[0][t], v, acc);
        }
        out[i * DOUT + f] = acc;               // s_in
        out[NN * DOUT + i * DOUT + f] = 0.f;   // zero s_out row i for kernel C
    }
}

// ---------------------------------------------------------------------------
// Kernel C: s_out gather. Grid (8 j-tiles, 37 i-tiles) = 296 blocks,
// 2 CTAs/SM (launch_bounds caps regs at 64). cp.async ping-pong staging of
// T[i] rows 0..49; row 50 is a zero sentinel so masked-off entries are
// added branch-free. Each warp owns 8 j-columns; lanes cover dims:
//   lane L -> dims (2L, 2L+1) as float2; lanes 0..5 -> dim 64+L (scalar).
// ---------------------------------------------------------------------------
#define JT 128
#define IT 28
#define CTHREADS 512
#define JPW 8   // JT / 16 warps

__device__ __forceinline__ void cp16(unsigned dst, const void* src) {
    asm volatile("cp.async.cg.shared.global [%0], [%1], 16;" :: "r"(dst), "l"(src));
}

__global__ __launch_bounds__(CTHREADS, 2) void col_kernel(
    const int* __restrict__ matrix,
    const int* __restrict__ mask,
    float* __restrict__ sout)   // out + N*DOUT, zeroed by row_kernel
{
    __shared__ float Tsh[2][TROWS * TSTRIDE];   // 2 x 14.7 KB
    __shared__ int   codes[2][JT];

    const int jbase = blockIdx.x * JT;
    const int i0 = blockIdx.y * IT;
    const int i1 = min(i0 + IT, NN);
    const int tid = threadIdx.x;
    const int w = tid >> 5, lane = tid & 31;

    float2 a0[JPW];
    float  a1[JPW];
    #pragma unroll
    for (int q = 0; q < JPW; q++) { a0[q] = make_float2(0.f, 0.f); a1[q] = 0.f; }

    const unsigned ts0 = (unsigned)__cvta_generic_to_shared(&Tsh[0][0]);
    const unsigned ts1 = (unsigned)__cvta_generic_to_shared(&Tsh[1][0]);

    // zero the sentinel row (row 50) of both buffers — never touched by cp.async
    if (tid < TSTRIDE) {
        Tsh[0][NTYPE * TSTRIDE + tid] = 0.f;
        Tsh[1][NTYPE * TSTRIDE + tid] = 0.f;
    }

    // prologue: stage i0 (rows 0..49 = 900 float4)
    {
        const float4* src = (const float4*)(g_T + (size_t)i0 * NTYPE * TSTRIDE);
        cp16(ts0 + tid * 16, src + tid);
        if (tid < 388) cp16(ts0 + (512 + tid) * 16, src + 512 + tid);
        asm volatile("cp.async.commit_group;");
    }
    int pcode = 0;
    if (tid < JT) {
        int j = jbase + tid;
        int2 tt = ((const int2*)matrix)[(size_t)i0 * NN + j];
        int2 mm = ((const int2*)mask)[(size_t)i0 * NN + j];
        pcode = (mm.x ? tt.x : NTYPE) | ((mm.y ? tt.y : NTYPE) << 8);
    }

    for (int i = i0; i < i1; i++) {
        const int buf = (i - i0) & 1;

        asm volatile("cp.async.wait_group 0;" ::: "memory");  // T[i] landed
        if (tid < JT) codes[buf][tid] = pcode;
        __syncthreads();   // T[i]+codes[i] visible; gathers of i-1 from buf^1 done

        if (i + 1 < i1) {
            const float4* src = (const float4*)(g_T + (size_t)(i + 1) * NTYPE * TSTRIDE);
            const unsigned dst = (buf ^ 1) ? ts1 : ts0;
            cp16(dst + tid * 16, src + tid);
            if (tid < 388) cp16(dst + (512 + tid) * 16, src + 512 + tid);
            asm volatile("cp.async.commit_group;");
            if (tid < JT) {
                int j = jbase + tid;
                int2 tt = ((const int2*)matrix)[(size_t)(i + 1) * NN + j];
                int2 mm = ((const int2*)mask)[(size_t)(i + 1) * NN + j];
                pcode = (mm.x ? tt.x : NTYPE) | ((mm.y ? tt.y : NTYPE) << 8);
            }
        }

        // branch-free gather for row i
        const float* Tb = Tsh[buf];
        const int* cb = codes[buf];
        const int jb = w * JPW;
        #pragma unroll
        for (int q = 0; q < JPW; q++) {
            int code = cb[jb + q];            // warp-uniform broadcast
            const float* r0 = Tb + (code & 0xFF) * TSTRIDE;
            const float* r1 = Tb + (code >> 8) * TSTRIDE;
            float2 v0 = ((const float2*)r0)[lane];
            float2 v1 = ((const float2*)r1)[lane];
            a0[q].x += v0.x + v1.x;
            a0[q].y += v0.y + v1.y;
            if (lane < 6) a1[q] += r0[64 + lane] + r1[64 + lane];
        }
    }

    // combine partials across the 37 i-tiles (vector reductions)
    #pragma unroll
    for (int q = 0; q < JPW; q++) {
        int j = jbase + w * JPW + q;
        float* base = sout + (size_t)j * DOUT;
        asm volatile("red.global.add.v2.f32 [%0], {%1, %2};"
                     :: "l"(base + 2 * lane), "f"(a0[q].x), "f"(a0[q].y) : "memory");
        if (lane < 6) atomicAdd(base + 64 + lane, a1[q]);
    }
}

// ---------------------------------------------------------------------------
extern "C" void kernel_launch(void* const* d_in, const int* in_sizes, int n_in,
                              void* d_out, int out_size)
{
    const float* h      = (const float*)d_in[0];
    const float* emb    = (const float*)d_in[1];
    const float* W      = (const float*)d_in[2];
    const float* bvec   = (const float*)d_in[3];
    const int*   matrix = (const int*)d_in[4];
    const int*   mask   = (const int*)d_in[5];
    float* out = (float*)d_out;

    row_kernel<<<NN, 128>>>(h, emb, W, bvec, matrix, mask, out);
    col_kernel<<<dim3(8, 37), CTHREADS>>>(matrix, mask, out + NN * DOUT);
}